// round 1
// baseline (speedup 1.0000x reference)
#include <cuda_runtime.h>

// Problem constants: T=4, B=16, N=1024, D=512, heads irrelevant (reshapes cancel).
#define TT     4
#define DD     512
#define MM     16384                 // B*N
#define MROWS  (TT * MM)             // 65536 GEMM rows
#define MD     (MM * DD)             // 8388608 elements per timestep

// Scratch (device globals: the sanctioned alloc-free workaround).
// g_Uq doubles as the S buffer (read-then-overwrite per thread in the LIF kernel).
__device__ float g_Uq[(size_t)MROWS * DD];
__device__ float g_Uk[(size_t)MROWS * DD];
__device__ float g_Uv[(size_t)MROWS * DD];

// ---------------------------------------------------------------------------
// C[m,n] = sum_k A[m,k] * W[n,k]  (+ bias[n] if bias != nullptr)
// A: MROWS x 512 row-major, W: 512 x 512 row-major. Classic 128x128x8 tile,
// 256 threads, 8x8 micro-tile per thread, fp32 FFMA accumulation (exact).
// ---------------------------------------------------------------------------
__global__ __launch_bounds__(256) void gemm_nt_512(
    const float* __restrict__ A, const float* __restrict__ W,
    const float* __restrict__ bias, float* __restrict__ C)
{
    __shared__ float As[8][128];
    __shared__ float Ws[8][128];

    const int bn  = blockIdx.x * 128;
    const int bm  = blockIdx.y * 128;
    const int tid = threadIdx.x;
    const int lr  = tid >> 1;          // load row within tile: 0..127
    const int lc  = (tid & 1) << 2;    // load col group: 0 or 4
    const int tx  = tid & 15;          // 16x16 thread grid
    const int ty  = tid >> 4;

    const float* Ap = A + (size_t)(bm + lr) * DD + lc;
    const float* Wp = W + (size_t)(bn + lr) * DD + lc;

    float acc[8][8];
#pragma unroll
    for (int i = 0; i < 8; i++)
#pragma unroll
        for (int j = 0; j < 8; j++) acc[i][j] = 0.0f;

    for (int k0 = 0; k0 < DD; k0 += 8) {
        float4 a = *reinterpret_cast<const float4*>(Ap + k0);
        float4 w = *reinterpret_cast<const float4*>(Wp + k0);
        As[lc + 0][lr] = a.x; As[lc + 1][lr] = a.y;
        As[lc + 2][lr] = a.z; As[lc + 3][lr] = a.w;
        Ws[lc + 0][lr] = w.x; Ws[lc + 1][lr] = w.y;
        Ws[lc + 2][lr] = w.z; Ws[lc + 3][lr] = w.w;
        __syncthreads();

#pragma unroll
        for (int k = 0; k < 8; k++) {
            float ra[8], rb[8];
#pragma unroll
            for (int i = 0; i < 8; i++) ra[i] = As[k][ty * 8 + i];
#pragma unroll
            for (int j = 0; j < 8; j++) rb[j] = Ws[k][tx * 8 + j];
#pragma unroll
            for (int i = 0; i < 8; i++)
#pragma unroll
                for (int j = 0; j < 8; j++)
                    acc[i][j] = fmaf(ra[i], rb[j], acc[i][j]);
        }
        __syncthreads();
    }

#pragma unroll
    for (int i = 0; i < 8; i++) {
        float* Crow = C + (size_t)(bm + ty * 8 + i) * DD + bn + tx * 8;
#pragma unroll
        for (int j = 0; j < 8; j += 4) {
            float4 o;
            o.x = acc[i][j + 0]; o.y = acc[i][j + 1];
            o.z = acc[i][j + 2]; o.w = acc[i][j + 3];
            if (bias) {
                const int col = bn + tx * 8 + j;
                o.x += bias[col + 0]; o.y += bias[col + 1];
                o.z += bias[col + 2]; o.w += bias[col + 3];
            }
            *reinterpret_cast<float4*>(Crow + j) = o;
        }
    }
}

// ---------------------------------------------------------------------------
// LIF over time for q/k/v potentials + causal linear attention combine.
// Per element i (flat M*D): for t = 0..3:
//   mem = 0.9*mem + u; spike = (mem >= 1); mem -= spike;
//   ctx += sk*sv;  s[t,i] = sq * ctx;
// S is written in-place over Uq (read happens before the write, same thread).
// ---------------------------------------------------------------------------
__global__ __launch_bounds__(256) void lif_combine_kernel(
    float* __restrict__ Uq, const float* __restrict__ Uk,
    const float* __restrict__ Uv)
{
    const int i = blockIdx.x * blockDim.x + threadIdx.x;   // float4 index
    const float4* uq = reinterpret_cast<const float4*>(Uq);
    const float4* uk = reinterpret_cast<const float4*>(Uk);
    const float4* uv = reinterpret_cast<const float4*>(Uv);
    float4* s4 = reinterpret_cast<float4*>(Uq);

    float mq[4] = {0.f, 0.f, 0.f, 0.f};
    float mk[4] = {0.f, 0.f, 0.f, 0.f};
    float mv[4] = {0.f, 0.f, 0.f, 0.f};
    float cx[4] = {0.f, 0.f, 0.f, 0.f};

    const int step = MD / 4;
#pragma unroll
    for (int t = 0; t < TT; t++) {
        const int off = t * step + i;
        const float4 a = uq[off];
        const float4 b = uk[off];
        const float4 c = uv[off];
        const float qa[4] = {a.x, a.y, a.z, a.w};
        const float kb[4] = {b.x, b.y, b.z, b.w};
        const float vc[4] = {c.x, c.y, c.z, c.w};
        float out[4];
#pragma unroll
        for (int j = 0; j < 4; j++) {
            mq[j] = 0.9f * mq[j] + qa[j];
            const float sq = (mq[j] >= 1.0f) ? 1.0f : 0.0f;
            mq[j] -= sq;
            mk[j] = 0.9f * mk[j] + kb[j];
            const float sk = (mk[j] >= 1.0f) ? 1.0f : 0.0f;
            mk[j] -= sk;
            mv[j] = 0.9f * mv[j] + vc[j];
            const float sv = (mv[j] >= 1.0f) ? 1.0f : 0.0f;
            mv[j] -= sv;
            cx[j] += sk * sv;
            out[j] = sq * cx[j];
        }
        s4[off] = make_float4(out[0], out[1], out[2], out[3]);
    }
}

// ---------------------------------------------------------------------------
// Launch: 3 projection GEMMs -> LIF/combine -> output GEMM (+bias) into d_out.
// Graph-capturable: kernel launches + symbol-address queries only.
// ---------------------------------------------------------------------------
extern "C" void kernel_launch(void* const* d_in, const int* in_sizes, int n_in,
                              void* d_out, int out_size)
{
    const float* x   = (const float*)d_in[0];   // (T,B,N,D) = (65536, 512)
    const float* Wq  = (const float*)d_in[1];
    const float* Wk  = (const float*)d_in[2];
    const float* Wv  = (const float*)d_in[3];
    const float* Wp  = (const float*)d_in[4];
    const float* bp  = (const float*)d_in[5];
    float* out = (float*)d_out;

    float *Uq, *Uk, *Uv;
    cudaGetSymbolAddress((void**)&Uq, g_Uq);
    cudaGetSymbolAddress((void**)&Uk, g_Uk);
    cudaGetSymbolAddress((void**)&Uv, g_Uv);

    const dim3 grid(DD / 128, MROWS / 128);   // (4, 512)

    gemm_nt_512<<<grid, 256>>>(x, Wq, nullptr, Uq);
    gemm_nt_512<<<grid, 256>>>(x, Wk, nullptr, Uk);
    gemm_nt_512<<<grid, 256>>>(x, Wv, nullptr, Uv);

    lif_combine_kernel<<<(MD / 4) / 256, 256>>>(Uq, Uk, Uv);

    gemm_nt_512<<<grid, 256>>>(Uq /* = S */, Wp, bp, out);
}

// round 5
// speedup vs baseline: 1.0832x; 1.0832x over previous
#include <cuda_runtime.h>
#include <cuda_bf16.h>
#include <cstdint>
#include <cstddef>

// Shapes: T=4, B=16, N=1024, D=512 -> GEMM rows 65536, heads cancel.
#define TT     4
#define DD     512
#define MM     16384
#define MROWS  65536
#define NPROJ  1536            // Wq|Wk|Wv stacked
#define KPROJ  3072            // 6 bf16 limb-product terms * 512
#define KFIN   1024            // 2 terms * 512
#define EPS    1e-3f           // near-threshold repair margin (error ~1e-6)
#define MAXF   (1 << 20)       // worklist capacity (expect ~5e4)

// a-limb index per 512-col term block (nibbles, terms t=0..5): {0,0,1,0,1,2}
#define AMAP_PROJ 0x00210100u
#define AMAP_FIN  0x00000000u

// ---------------- scratch (device globals) ----------------
__device__ __nv_bfloat16 g_Aex [(size_t)MROWS * 1536];   // x limbs: [m][limb*512 + k]
__device__ float         g_U   [(size_t)MROWS * 1536];   // q|k|v potentials per row
__device__ __nv_bfloat16 g_Sex [(size_t)MROWS * 512];    // S (exact in bf16)
__device__ __nv_bfloat16 g_Wex [(size_t)NPROJ * KPROJ];  // expanded W limb terms
__device__ __nv_bfloat16 g_Wpex[(size_t)512 * KFIN];     // [Wp_hi | Wp_lo]
__device__ int  g_cnt;
__device__ int2 g_list[MAXF];

// ---------------- helpers ----------------
__device__ __forceinline__ uint32_t smem_u32(const void* p) {
    uint32_t a;
    asm("{ .reg .u64 t; cvta.to.shared.u64 t, %1; cvt.u32.u64 %0, t; }" : "=r"(a) : "l"(p));
    return a;
}
#define SW128(o) ((o) ^ (((o) >> 3) & 0x70))
#define CP_ASYNC16(dst, src) \
    asm volatile("cp.async.cg.shared.global [%0], [%1], 16;" :: "r"(dst), "l"(src))
#define CP_COMMIT() asm volatile("cp.async.commit_group;" ::: "memory")

__device__ __forceinline__ void ldmatrix_x4(uint32_t* r, uint32_t addr) {
    asm volatile("ldmatrix.sync.aligned.m8n8.x4.shared.b16 {%0,%1,%2,%3}, [%4];"
                 : "=r"(r[0]), "=r"(r[1]), "=r"(r[2]), "=r"(r[3]) : "r"(addr));
}
__device__ __forceinline__ void mma_bf16(float* d, const uint32_t* a, uint32_t b0, uint32_t b1) {
    asm volatile("mma.sync.aligned.m16n8k16.row.col.f32.bf16.bf16.f32 "
                 "{%0,%1,%2,%3}, {%4,%5,%6,%7}, {%8,%9}, {%0,%1,%2,%3};"
                 : "+f"(d[0]), "+f"(d[1]), "+f"(d[2]), "+f"(d[3])
                 : "r"(a[0]), "r"(a[1]), "r"(a[2]), "r"(a[3]), "r"(b0), "r"(b1));
}

// ---------------- limb split (exact two-sum residuals) ----------------
__device__ __forceinline__ void split3(float x, __nv_bfloat16& h, __nv_bfloat16& m, __nv_bfloat16& l) {
    h = __float2bfloat16(x);
    float r = x - __bfloat162float(h);
    m = __float2bfloat16(r);
    r = r - __bfloat162float(m);
    l = __float2bfloat16(r);
}

__global__ __launch_bounds__(256) void split_x_kernel(const float* __restrict__ x,
                                                      __nv_bfloat16* __restrict__ Aex) {
    size_t i = (size_t)blockIdx.x * blockDim.x + threadIdx.x;   // float4 index
    size_t row = i / (DD / 4);
    int k4 = (int)(i % (DD / 4)) * 4;
    float4 v = reinterpret_cast<const float4*>(x)[i];
    float vs[4] = {v.x, v.y, v.z, v.w};
    __nv_bfloat16 h[4], m[4], l[4];
#pragma unroll
    for (int j = 0; j < 4; j++) split3(vs[j], h[j], m[j], l[j]);
    __nv_bfloat16* base = Aex + row * 1536 + k4;
    *reinterpret_cast<__nv_bfloat162*>(base +    0) = __halves2bfloat162(h[0], h[1]);
    *reinterpret_cast<__nv_bfloat162*>(base +    2) = __halves2bfloat162(h[2], h[3]);
    *reinterpret_cast<__nv_bfloat162*>(base +  512) = __halves2bfloat162(m[0], m[1]);
    *reinterpret_cast<__nv_bfloat162*>(base +  514) = __halves2bfloat162(m[2], m[3]);
    *reinterpret_cast<__nv_bfloat162*>(base + 1024) = __halves2bfloat162(l[0], l[1]);
    *reinterpret_cast<__nv_bfloat162*>(base + 1026) = __halves2bfloat162(l[2], l[3]);
}

// Wex[n, t*512+k] = limb_{wl[t]}(W); wl = {0,1,0,2,1,0} paired with a {0,0,1,0,1,2}
// -> terms hh, hm, mh, hl, mm, lh (all limb-sum <= 2)
__global__ __launch_bounds__(256) void split_w_kernel(const float* __restrict__ Wq,
                                                      const float* __restrict__ Wk,
                                                      const float* __restrict__ Wv,
                                                      __nv_bfloat16* __restrict__ Wex) {
    int i = blockIdx.x * blockDim.x + threadIdx.x;   // over 1536 * 128
    int n = i >> 7;
    int k4 = (i & 127) * 4;
    const float* Wsrc = (n < 512) ? Wq : (n < 1024 ? Wk : Wv);
    const float* src = Wsrc + (size_t)(n & 511) * DD + k4;
    __nv_bfloat16 h[4], m[4], l[4];
#pragma unroll
    for (int j = 0; j < 4; j++) split3(src[j], h[j], m[j], l[j]);
    __nv_bfloat16* base = Wex + (size_t)n * KPROJ + k4;
    const int wl[6] = {0, 1, 0, 2, 1, 0};
#pragma unroll
    for (int t = 0; t < 6; t++) {
        const __nv_bfloat16* a = (wl[t] == 0) ? h : (wl[t] == 1 ? m : l);
        *reinterpret_cast<__nv_bfloat162*>(base + t * 512)     = __halves2bfloat162(a[0], a[1]);
        *reinterpret_cast<__nv_bfloat162*>(base + t * 512 + 2) = __halves2bfloat162(a[2], a[3]);
    }
}

__global__ __launch_bounds__(256) void split_wp_kernel(const float* __restrict__ Wp,
                                                       __nv_bfloat16* __restrict__ Wpex) {
    int i = blockIdx.x * blockDim.x + threadIdx.x;   // over 512 * 128
    int n = i >> 7;
    int k4 = (i & 127) * 4;
    const float* src = Wp + (size_t)n * DD + k4;
    __nv_bfloat16 h[4], l[4];
#pragma unroll
    for (int j = 0; j < 4; j++) {
        h[j] = __float2bfloat16(src[j]);
        l[j] = __float2bfloat16(src[j] - __bfloat162float(h[j]));
    }
    __nv_bfloat16* base = Wpex + (size_t)n * KFIN + k4;
    *reinterpret_cast<__nv_bfloat162*>(base)           = __halves2bfloat162(h[0], h[1]);
    *reinterpret_cast<__nv_bfloat162*>(base + 2)       = __halves2bfloat162(h[2], h[3]);
    *reinterpret_cast<__nv_bfloat162*>(base + 512)     = __halves2bfloat162(l[0], l[1]);
    *reinterpret_cast<__nv_bfloat162*>(base + 512 + 2) = __halves2bfloat162(l[2], l[3]);
}

__global__ void reset_cnt_kernel() { g_cnt = 0; }

// ---------------------------------------------------------------------------
// C[M,N] = A*B^T via mma.sync bf16 (fp32 accum). BM=128 BN=128 BK=64, 3-stage
// cp.async pipeline, SW128 smem, 8 warps (2 m x 4 n), warp tile 64x32.
// ---------------------------------------------------------------------------
__global__ __launch_bounds__(256, 2) void gemm_mma_bf16(
    const __nv_bfloat16* __restrict__ A, int lda, uint32_t amap,
    const __nv_bfloat16* __restrict__ B, int K,
    float* __restrict__ C, int ldc, const float* __restrict__ bias)
{
    extern __shared__ __align__(1024) char smem[];     // 3 stages x (16KB A + 16KB B)
    const int tid = threadIdx.x;
    const int l   = tid & 31;
    const int wid = tid >> 5;
    const int m_base = blockIdx.y * 128;
    const int n_base = blockIdx.x * 128;
    const int wm = (wid & 1) * 64;
    const int wn = (wid >> 1) * 32;
    const uint32_t sbase = smem_u32(smem);
    const int nc = K >> 6;

    const int arow = tid >> 3, aseg = tid & 7;
    const uint32_t sOff = SW128((uint32_t)(arow * 128 + aseg * 16));
    const __nv_bfloat16* Abase = A + (size_t)(m_base + arow) * lda + aseg * 8;
    const __nv_bfloat16* Bbase = B + (size_t)(n_base + arow) * K + aseg * 8;

    auto issue = [&](int c, int stg) {
        const int kc0 = c << 6;
        const int acol0 = (int)((amap >> ((kc0 >> 9) * 4)) & 7) * 512 + (kc0 & 511);
        const uint32_t sa = sbase + stg * 32768 + sOff;
        const uint32_t sb = sa + 16384;
        const __nv_bfloat16* ga = Abase + acol0;
        const __nv_bfloat16* gb = Bbase + kc0;
#pragma unroll
        for (int i = 0; i < 4; i++) CP_ASYNC16(sa + i * 4096, ga + (size_t)i * 32 * lda);
#pragma unroll
        for (int i = 0; i < 4; i++) CP_ASYNC16(sb + i * 4096, gb + (size_t)i * 32 * K);
        CP_COMMIT();
    };

    issue(0, 0);
    issue(1, 1);

    const uint32_t aoff0 = (uint32_t)((wm + (l & 15)) * 128 + (l >> 4) * 16);
    const uint32_t boff0 = (uint32_t)((wn + (l & 7) + ((l >> 4) << 3)) * 128 + ((l >> 3) & 1) * 16);

    float acc[4][4][4];
#pragma unroll
    for (int mt = 0; mt < 4; mt++)
#pragma unroll
        for (int nt = 0; nt < 4; nt++)
#pragma unroll
            for (int q = 0; q < 4; q++) acc[mt][nt][q] = 0.0f;

    for (int c = 0; c < nc; ++c) {
        if (c + 1 < nc) asm volatile("cp.async.wait_group 1;" ::: "memory");
        else            asm volatile("cp.async.wait_group 0;" ::: "memory");
        __syncthreads();

        const uint32_t abase = sbase + (c % 3) * 32768;
        const uint32_t bbase = abase + 16384;
#pragma unroll
        for (int ks = 0; ks < 4; ++ks) {
            uint32_t a[4][4], b[2][4];
#pragma unroll
            for (int mt = 0; mt < 4; ++mt)
                ldmatrix_x4(a[mt], abase + SW128(aoff0 + mt * 2048 + ks * 32));
#pragma unroll
            for (int p = 0; p < 2; ++p)
                ldmatrix_x4(b[p], bbase + SW128(boff0 + p * 2048 + ks * 32));
#pragma unroll
            for (int mt = 0; mt < 4; ++mt)
#pragma unroll
                for (int nt = 0; nt < 4; ++nt)
                    mma_bf16(acc[mt][nt], a[mt],
                             b[nt >> 1][(nt & 1) * 2], b[nt >> 1][(nt & 1) * 2 + 1]);
        }
        if (c + 2 < nc) issue(c + 2, (c + 2) % 3);
    }

#pragma unroll
    for (int mt = 0; mt < 4; ++mt) {
        const int m0 = m_base + wm + mt * 16 + (l >> 2);
#pragma unroll
        for (int nt = 0; nt < 4; ++nt) {
            const int n = n_base + wn + nt * 8 + (l & 3) * 2;
            float bx = 0.0f, by = 0.0f;
            if (bias) { bx = bias[n]; by = bias[n + 1]; }
            float2 v0 = make_float2(acc[mt][nt][0] + bx, acc[mt][nt][1] + by);
            float2 v1 = make_float2(acc[mt][nt][2] + bx, acc[mt][nt][3] + by);
            *reinterpret_cast<float2*>(C + (size_t)m0 * ldc + n) = v0;
            *reinterpret_cast<float2*>(C + (size_t)(m0 + 8) * ldc + n) = v1;
        }
    }
}

// ---------------- LIF + combine + near-threshold flagging ----------------
__global__ __launch_bounds__(256) void lif_combine_kernel(
    const float* __restrict__ U, __nv_bfloat16* __restrict__ Sex)
{
    const int i = blockIdx.x * blockDim.x + threadIdx.x;   // float4 index in (MM*DD/4)
    const int mm = i / (DD / 4);
    const int d4 = (i % (DD / 4)) * 4;

    float mq[4] = {0.f, 0.f, 0.f, 0.f};
    float mk[4] = {0.f, 0.f, 0.f, 0.f};
    float mv[4] = {0.f, 0.f, 0.f, 0.f};
    float cx[4] = {0.f, 0.f, 0.f, 0.f};
    bool near[4] = {false, false, false, false};

#pragma unroll
    for (int t = 0; t < TT; t++) {
        const size_t rb = (size_t)(t * MM + mm) * 1536 + d4;
        const float4 a  = *reinterpret_cast<const float4*>(U + rb);
        const float4 b  = *reinterpret_cast<const float4*>(U + rb + 512);
        const float4 cc = *reinterpret_cast<const float4*>(U + rb + 1024);
        const float qa[4] = {a.x, a.y, a.z, a.w};
        const float kb[4] = {b.x, b.y, b.z, b.w};
        const float vc[4] = {cc.x, cc.y, cc.z, cc.w};
        __nv_bfloat16 s[4];
#pragma unroll
        for (int j = 0; j < 4; j++) {
            mq[j] = 0.9f * mq[j] + qa[j];
            const float sq = (mq[j] >= 1.0f) ? 1.0f : 0.0f;
            mk[j] = 0.9f * mk[j] + kb[j];
            const float sk = (mk[j] >= 1.0f) ? 1.0f : 0.0f;
            mv[j] = 0.9f * mv[j] + vc[j];
            const float sv = (mv[j] >= 1.0f) ? 1.0f : 0.0f;
            near[j] = near[j] | (fabsf(mq[j] - 1.0f) < EPS)
                              | (fabsf(mk[j] - 1.0f) < EPS)
                              | (fabsf(mv[j] - 1.0f) < EPS);
            mq[j] -= sq; mk[j] -= sk; mv[j] -= sv;
            cx[j] += sk * sv;
            s[j] = __float2bfloat16(sq * cx[j]);   // integer 0..4: exact in bf16
        }
        __nv_bfloat16* sp = Sex + (size_t)(t * MM + mm) * 512 + d4;
        *reinterpret_cast<__nv_bfloat162*>(sp)     = __halves2bfloat162(s[0], s[1]);
        *reinterpret_cast<__nv_bfloat162*>(sp + 2) = __halves2bfloat162(s[2], s[3]);
    }
#pragma unroll
    for (int j = 0; j < 4; j++) {
        if (near[j]) {
            int idx = atomicAdd(&g_cnt, 1);
            if (idx < MAXF) g_list[idx] = make_int2(mm, d4 + j);
        }
    }
}

// ---------------- exact repair: serial fp32 FMA (reference bit order) -------
__global__ __launch_bounds__(128) void fix_kernel(
    const float* __restrict__ x,  const float* __restrict__ Wq,
    const float* __restrict__ Wk, const float* __restrict__ Wv,
    __nv_bfloat16* __restrict__ Sex)
{
    const int cnt = min(g_cnt, MAXF);
    for (int i = blockIdx.x * blockDim.x + threadIdx.x; i < cnt;
         i += gridDim.x * blockDim.x) {
        const int mm = g_list[i].x;
        const int d  = g_list[i].y;
        const float* wq = Wq + (size_t)d * DD;
        const float* wk = Wk + (size_t)d * DD;
        const float* wv = Wv + (size_t)d * DD;

        float mq = 0.f, mk = 0.f, mv = 0.f, cx = 0.f;
#pragma unroll 1
        for (int t = 0; t < TT; t++) {
            const float* xr = x + (size_t)(t * MM + mm) * DD;
            float uq = 0.f, uk = 0.f, uv = 0.f;
#pragma unroll 1
            for (int k = 0; k < DD; k++) {
                const float xv = xr[k];
                uq = fmaf(xv, wq[k], uq);
                uk = fmaf(xv, wk[k], uk);
                uv = fmaf(xv, wv[k], uv);
            }
            mq = 0.9f * mq + uq;
            const float sq = (mq >= 1.0f) ? 1.0f : 0.0f;
            mq -= sq;
            mk = 0.9f * mk + uk;
            const float sk = (mk >= 1.0f) ? 1.0f : 0.0f;
            mk -= sk;
            mv = 0.9f * mv + uv;
            const float sv = (mv >= 1.0f) ? 1.0f : 0.0f;
            mv -= sv;
            cx += sk * sv;
            Sex[(size_t)(t * MM + mm) * 512 + d] = __float2bfloat16(sq * cx);
        }
    }
}

// ---------------- launch ----------------
extern "C" void kernel_launch(void* const* d_in, const int* in_sizes, int n_in,
                              void* d_out, int out_size)
{
    const float* x  = (const float*)d_in[0];
    const float* Wq = (const float*)d_in[1];
    const float* Wk = (const float*)d_in[2];
    const float* Wv = (const float*)d_in[3];
    const float* Wp = (const float*)d_in[4];
    const float* bp = (const float*)d_in[5];
    float* out = (float*)d_out;

    __nv_bfloat16 *Aex, *Sex, *Wex, *Wpex;
    float* U;
    cudaGetSymbolAddress((void**)&Aex,  g_Aex);
    cudaGetSymbolAddress((void**)&U,    g_U);
    cudaGetSymbolAddress((void**)&Sex,  g_Sex);
    cudaGetSymbolAddress((void**)&Wex,  g_Wex);
    cudaGetSymbolAddress((void**)&Wpex, g_Wpex);

    const int SMEM_BYTES = 3 * 32768;   // 96KB dynamic
    cudaFuncSetAttribute(gemm_mma_bf16, cudaFuncAttributeMaxDynamicSharedMemorySize, SMEM_BYTES);

    split_x_kernel<<<(MROWS * (DD / 4)) / 256, 256>>>(x, Aex);
    split_w_kernel<<<(NPROJ * 128) / 256, 256>>>(Wq, Wk, Wv, Wex);
    split_wp_kernel<<<(512 * 128) / 256, 256>>>(Wp, Wpex);
    reset_cnt_kernel<<<1, 1>>>();

    // fused Q/K/V projection: [65536,3072] x [1536,3072]^T -> U [65536,1536]
    gemm_mma_bf16<<<dim3(NPROJ / 128, MROWS / 128), 256, SMEM_BYTES>>>(
        Aex, 1536, AMAP_PROJ, Wex, KPROJ, U, 1536, nullptr);

    lif_combine_kernel<<<(MM * (DD / 4)) / 256, 256>>>(U, Sex);

    // exact repair of near-threshold columns (expected ~5e4 entries)
    fix_kernel<<<512, 128>>>(x, Wq, Wk, Wv, Sex);

    // output projection: [65536,1024] x [512,1024]^T -> out [65536,512]
    gemm_mma_bf16<<<dim3(512 / 128, MROWS / 128), 256, SMEM_BYTES>>>(
        Sex, 512, AMAP_FIN, Wpex, KFIN, out, 512, bp);
}